// round 14
// baseline (speedup 1.0000x reference)
#include <cuda_runtime.h>
#include <cuda_bf16.h>
#include <cstdint>

// AdaBoost fused classifier via legacy mma.sync TF32 (base-ISA sm_103).
//   logits[N,E] = x[N,F] @ W[E,F]^T + b
//   pred = (logit > 0); acc = sum_e pred*trunc(alpha); out = sign(acc)
// |logit| < TAU rescued by warp-cooperative exact fp32 recompute.
//
// R9 champion skeleton (BM=64, 256 thr, 2 CTAs/SM, warp tile 32x64,
// cp.async B double-buffer, fragment-order smem, R9 A path) with ONE
// change: B fragments are ks-PAIR-packed so one LDS.128 loads both
// k-steps of a fragment. Mainloop LDS issues/warp-chunk: 40 -> 24.

#define F_DIM 512
#define E_DIM 256
#define BM 64
#define BK 32
#define NCHUNK (F_DIM / BK)   // 16
#define TAU 4e-3f
#define QCAP 512

#define AREG 132                     // words per A fragment region (128 + 4 pad)
#define A_WORDS (16 * AREG)          // 2112 per buffer
#define B_WORDS 8192                 // per buffer (256n x 32k, ks-pair order)
#define DSMEM_BYTES ((2 * A_WORDS + 2 * B_WORDS) * 4)   // 82432

// W tf32, ks-pair fragment order:
//   word = t*8192 + wn*2048 + ksP*1024 + nt*128 + lane*4 + (ks&1)*2 + khi
__device__ uint32_t g_Wfrag[E_DIM * F_DIM];

static __device__ __forceinline__ uint32_t to_tf32(float x) {
    uint32_t r;
    asm("cvt.rna.tf32.f32 %0, %1;" : "=r"(r) : "f"(x));
    return r;
}
static __device__ __forceinline__ uint32_t smem_u32(const void* p) {
    uint32_t a;
    asm("{ .reg .u64 t; cvta.to.shared.u64 t, %1; cvt.u32.u64 %0, t; }"
        : "=r"(a) : "l"(p));
    return a;
}

#define CP_ASYNC16(dst, src) \
    asm volatile("cp.async.ca.shared.global [%0], [%1], 16;" \
                 :: "r"(dst), "l"(src) : "memory")
#define CP_COMMIT() asm volatile("cp.async.commit_group;" ::: "memory")
#define CP_WAIT_ALL() asm volatile("cp.async.wait_group 0;" ::: "memory")

#define MMA_TF32S(c, a, b0, b1)                                            \
    asm volatile(                                                          \
        "mma.sync.aligned.m16n8k8.row.col.f32.tf32.tf32.f32 "              \
        "{%0,%1,%2,%3}, {%4,%5,%6,%7}, {%8,%9}, {%0,%1,%2,%3};"            \
        : "+f"((c)[0]), "+f"((c)[1]), "+f"((c)[2]), "+f"((c)[3])           \
        : "r"((a)[0]), "r"((a)[1]), "r"((a)[2]), "r"((a)[3]),              \
          "r"(b0), "r"(b1))

// ---- prep: convert W to tf32, permute into ks-pair fragment order ----
__global__ void prep_kernel(const float* __restrict__ Wm) {
    int idx = blockIdx.x * blockDim.x + threadIdx.x;   // (n, k4)
    int n  = idx >> 7;
    int k4 = idx & 127;
    float4 v = *reinterpret_cast<const float4*>(Wm + (size_t)n * F_DIM + k4 * 4);
    uint32_t c0 = to_tf32(v.x), c1 = to_tf32(v.y);
    uint32_t c2 = to_tf32(v.z), c3 = to_tf32(v.w);

    int k0  = k4 * 4;
    int t   = k0 >> 5;
    int kin = k0 & 31;
    int ks  = kin >> 3;
    int khi = (kin >> 2) & 1;        // constant across the 4 elems
    int wn = n >> 6, nt = (n >> 3) & 7, g = n & 7;
    uint32_t base = (uint32_t)t * 8192 + wn * 2048 + (ks >> 1) * 1024 +
                    nt * 128 + g * 16 + (ks & 1) * 2 + khi;
    g_Wfrag[base + 0]  = c0;         // tg = 0..3 -> lane*4 stride 4
    g_Wfrag[base + 4]  = c1;
    g_Wfrag[base + 8]  = c2;
    g_Wfrag[base + 12] = c3;
}

__global__ __launch_bounds__(256, 2)
void adaboost_mma_kernel(const float* __restrict__ x,
                         const float* __restrict__ Wm,
                         const float* __restrict__ bvec,
                         const float* __restrict__ alphas,
                         float* __restrict__ out) {
    extern __shared__ uint32_t sm[];
    uint32_t* As = sm;                       // [2][16 regions][AREG]
    uint32_t* Bs = sm + 2 * A_WORDS;         // [2][8192] ks-pair order

    __shared__ float s_b[E_DIM];
    __shared__ float s_ta[E_DIM];
    __shared__ float psum[BM][4];
    __shared__ float s_rsum[BM];
    __shared__ int s_nresc;
    __shared__ uint32_t s_q[QCAP];

    const int tid  = threadIdx.x;
    const int wid  = tid >> 5;
    const int lane = tid & 31;
    const int g    = lane >> 2;
    const int tg   = lane & 3;
    const int wm   = wid & 1;      // 2 warp-rows (32 rows each)
    const int wn   = wid >> 1;     // 4 warp-cols (64 cols each)
    const int m0   = blockIdx.x * BM;

    s_b[tid]  = bvec[tid];
    s_ta[tid] = truncf(alphas[tid]);
    if (tid < BM) s_rsum[tid] = 0.0f;
    if (tid == 0) s_nresc = 0;

    const uint32_t Bs_u = smem_u32(Bs);

    float acc[2][8][4];
#pragma unroll
    for (int i = 0; i < 2; i++)
#pragma unroll
        for (int j = 0; j < 8; j++)
#pragma unroll
            for (int r = 0; r < 4; r++) acc[i][j][r] = 0.0f;

    // A mapping (R9): thread -> row a_row, k-octet a_ks
    const int a_row = tid >> 2;          // 0..63
    const int a_ks  = tid & 3;
    const int a_rt  = a_row >> 4;
    const int a_g   = a_row & 7;
    const int a_h   = (a_row >> 3) & 1;
    const uint32_t a_base = (uint32_t)(a_rt * 4 + a_ks) * AREG + a_g * 16 + a_h;

    // ---- prologue: chunk 0 ----
#pragma unroll
    for (int l = 0; l < 8; l++) {
        int u = tid + 256 * l;
        CP_ASYNC16(Bs_u + u * 16, (const char*)(g_Wfrag + u * 4));
    }
    CP_COMMIT();
#pragma unroll
    for (int hv = 0; hv < 2; hv++) {
        float4 v = *reinterpret_cast<const float4*>(
            x + (size_t)(m0 + a_row) * F_DIM + a_ks * 8 + hv * 4);
        uint32_t* dst = As + a_base + 2 * hv;
        dst[0]  = to_tf32(v.x);
        dst[4]  = to_tf32(v.y);
        dst[8]  = to_tf32(v.z);
        dst[12] = to_tf32(v.w);
    }

    // ---- main loop ----
    for (int t = 0; t < NCHUNK; t++) {
        const int p = t & 1;
        CP_WAIT_ALL();
        __syncthreads();   // A[p], B[p] visible; [p^1] free

        // issue B(t+1)
        if (t + 1 < NCHUNK) {
#pragma unroll
            for (int l = 0; l < 8; l++) {
                int u = tid + 256 * l;
                CP_ASYNC16(Bs_u + ((p ^ 1) * B_WORDS) * 4 + u * 16,
                           (const char*)(g_Wfrag + (t + 1) * B_WORDS + u * 4));
            }
        }
        CP_COMMIT();

        // A(t+1) -> regs
        float4 pa[2];
        if (t + 1 < NCHUNK) {
            const int kn = (t + 1) * BK;
#pragma unroll
            for (int hv = 0; hv < 2; hv++)
                pa[hv] = *reinterpret_cast<const float4*>(
                    x + (size_t)(m0 + a_row) * F_DIM + kn + a_ks * 8 + hv * 4);
        }

        // ---- compute on buffer p: ksP(2) x half(2) ----
        const uint32_t* Ap = As + p * A_WORDS;
        const uint32_t* Bp = Bs + p * B_WORDS + wn * 2048 + lane * 4;
#pragma unroll
        for (int kp = 0; kp < 2; kp++) {
            uint32_t afr[2][2][4];
#pragma unroll
            for (int mt = 0; mt < 2; mt++)
#pragma unroll
                for (int kk = 0; kk < 2; kk++) {
                    uint4 q = *reinterpret_cast<const uint4*>(
                        Ap + ((wm * 2 + mt) * 4 + kp * 2 + kk) * AREG + lane * 4);
                    afr[mt][kk][0] = q.x; afr[mt][kk][1] = q.y;
                    afr[mt][kk][2] = q.z; afr[mt][kk][3] = q.w;
                }
#pragma unroll
            for (int h = 0; h < 2; h++) {
                uint32_t bfr[4][4];
#pragma unroll
                for (int ntl = 0; ntl < 4; ntl++) {
                    uint4 q = *reinterpret_cast<const uint4*>(
                        Bp + kp * 1024 + (h * 4 + ntl) * 128);
                    bfr[ntl][0] = q.x; bfr[ntl][1] = q.y;
                    bfr[ntl][2] = q.z; bfr[ntl][3] = q.w;
                }
#pragma unroll
                for (int mt = 0; mt < 2; mt++)
#pragma unroll
                    for (int ntl = 0; ntl < 4; ntl++) {
                        const int nt = h * 4 + ntl;
                        MMA_TF32S(acc[mt][nt], afr[mt][0], bfr[ntl][0], bfr[ntl][1]);
                        MMA_TF32S(acc[mt][nt], afr[mt][1], bfr[ntl][2], bfr[ntl][3]);
                    }
            }
        }

        // ---- commit A(t+1) (R9 layout) ----
        if (t + 1 < NCHUNK) {
            uint32_t* An = As + (p ^ 1) * A_WORDS;
#pragma unroll
            for (int hv = 0; hv < 2; hv++) {
                uint32_t* dst = An + a_base + 2 * hv;
                dst[0]  = to_tf32(pa[hv].x);
                dst[4]  = to_tf32(pa[hv].y);
                dst[8]  = to_tf32(pa[hv].z);
                dst[12] = to_tf32(pa[hv].w);
            }
        }
    }

    // ---------------- epilogue ----------------
#pragma unroll
    for (int mt = 0; mt < 2; mt++) {
#pragma unroll
        for (int half = 0; half < 2; half++) {
            int rowl = wm * 32 + mt * 16 + g + half * 8;
            float s = 0.0f;
#pragma unroll
            for (int nt = 0; nt < 8; nt++) {
#pragma unroll
                for (int j = 0; j < 2; j++) {
                    int col = wn * 64 + nt * 8 + 2 * tg + j;
                    float logit = acc[mt][nt][half * 2 + j] + s_b[col];
                    if (fabsf(logit) < TAU) {
                        int qi = atomicAdd(&s_nresc, 1);
                        if (qi < QCAP) {
                            s_q[qi] = ((uint32_t)rowl << 8) | (uint32_t)col;
                        } else {
                            const float* xr = x + (size_t)(m0 + rowl) * F_DIM;
                            const float* wr = Wm + (size_t)col * F_DIM;
                            float a = 0.0f;
                            for (int f = 0; f < F_DIM; f++)
                                a = fmaf(__ldg(xr + f), __ldg(wr + f), a);
                            if (a + s_b[col] > 0.0f) s += s_ta[col];
                        }
                    } else if (logit > 0.0f) {
                        s += s_ta[col];
                    }
                }
            }
            s += __shfl_xor_sync(0xffffffffu, s, 1);
            s += __shfl_xor_sync(0xffffffffu, s, 2);
            if (tg == 0) psum[rowl][wn] = s;
        }
    }
    __syncthreads();

    // ---- warp-cooperative rescue ----
    {
        const int nresc = min(s_nresc, QCAP);
        for (int i = wid; i < nresc; i += 8) {
            uint32_t ent = s_q[i];
            int rowl = (int)(ent >> 8);
            int col  = (int)(ent & 0xFF);
            const float* xr = x + (size_t)(m0 + rowl) * F_DIM;
            const float* wr = Wm + (size_t)col * F_DIM;
            float a0 = 0.0f, a1 = 0.0f;
#pragma unroll
            for (int j = 0; j < 16; j += 2) {
                a0 = fmaf(__ldg(xr + j * 32 + lane), __ldg(wr + j * 32 + lane), a0);
                a1 = fmaf(__ldg(xr + (j + 1) * 32 + lane), __ldg(wr + (j + 1) * 32 + lane), a1);
            }
            float a = a0 + a1;
#pragma unroll
            for (int o = 16; o > 0; o >>= 1)
                a += __shfl_xor_sync(0xffffffffu, a, o);
            if (lane == 0 && a + s_b[col] > 0.0f)
                atomicAdd(&s_rsum[rowl], s_ta[col]);
        }
    }
    __syncthreads();

    if (tid < BM) {
        float s = psum[tid][0] + psum[tid][1] + psum[tid][2] + psum[tid][3]
                + s_rsum[tid];
        out[m0 + tid] = (s > 0.0f) ? 1.0f : ((s < 0.0f) ? -1.0f : 0.0f);
    }
}

extern "C" void kernel_launch(void* const* d_in, const int* in_sizes, int n_in,
                              void* d_out, int out_size) {
    const float* x      = (const float*)d_in[0];   // [N, F]
    const float* Wm     = (const float*)d_in[1];   // [E, F]
    const float* bvec   = (const float*)d_in[2];   // [E]
    const float* alphas = (const float*)d_in[3];   // [E]
    float* out = (float*)d_out;                    // [N]

    const int E = in_sizes[2];         // 256
    const int F = in_sizes[1] / E;     // 512
    const int N = in_sizes[0] / F;     // 131072

    (void)E; (void)F;
    prep_kernel<<<(E_DIM * (F_DIM / 4)) / 256, 256>>>(Wm);

    cudaFuncSetAttribute(adaboost_mma_kernel,
                         cudaFuncAttributeMaxDynamicSharedMemorySize, DSMEM_BYTES);
    adaboost_mma_kernel<<<N / BM, 256, DSMEM_BYTES>>>(x, Wm, bvec, alphas, out);
}

// round 15
// speedup vs baseline: 1.8510x; 1.8510x over previous
#include <cuda_runtime.h>
#include <cuda_bf16.h>
#include <cstdint>

// AdaBoost fused classifier via legacy mma.sync TF32 (base-ISA sm_103).
//   logits[N,E] = x[N,F] @ W[E,F]^T + b
//   pred = (logit > 0); acc = sum_e pred*trunc(alpha); out = sign(acc)
// |logit| < TAU rescued by warp-cooperative exact fp32 recompute.
//
// R9 skeleton (BM=64, 256 thr, 2 CTAs/SM, warp tile 32x64, cp.async B
// double-buffer) with ldmatrix-based fragment loads (register-neutral):
//   B: prep emits canonical 8x8-b16 matrices; 4x ldmatrix.x4 per ks
//      (was 8 LDS.64). A: 2x ldmatrix.x4 per ks.
//   A commit: 2 conflict-free STS.128 (was 8 conflicted STS.32).
// Mainloop smem instructions per warp-chunk: 48 -> 26. Regs unchanged.

#define F_DIM 512
#define E_DIM 256
#define BM 64
#define BK 32
#define NCHUNK (F_DIM / BK)   // 16
#define TAU 4e-3f
#define QCAP 512

#define AREG 136                     // words per A region (4 matrices + 8 pad)
#define A_WORDS (16 * AREG)          // 2176 per buffer
#define B_WORDS 8192                 // per buffer
#define DSMEM_BYTES ((2 * A_WORDS + 2 * B_WORDS) * 4)   // 82944

// W tf32 matrix order:
//   word = t*8192 + wn*2048 + ks*512 + nt*64 + w*32 + g*4 + tg
//   (each 32-word block = one 8x8 b16 matrix, lane-ordered)
__device__ uint32_t g_Wfrag[E_DIM * F_DIM];

static __device__ __forceinline__ uint32_t to_tf32(float x) {
    uint32_t r;
    asm("cvt.rna.tf32.f32 %0, %1;" : "=r"(r) : "f"(x));
    return r;
}
static __device__ __forceinline__ uint32_t smem_u32(const void* p) {
    uint32_t a;
    asm("{ .reg .u64 t; cvta.to.shared.u64 t, %1; cvt.u32.u64 %0, t; }"
        : "=r"(a) : "l"(p));
    return a;
}

#define CP_ASYNC16(dst, src) \
    asm volatile("cp.async.ca.shared.global [%0], [%1], 16;" \
                 :: "r"(dst), "l"(src) : "memory")
#define CP_COMMIT() asm volatile("cp.async.commit_group;" ::: "memory")
#define CP_WAIT_ALL() asm volatile("cp.async.wait_group 0;" ::: "memory")

#define LDSM_X4(r0, r1, r2, r3, addr)                                      \
    asm volatile(                                                          \
        "ldmatrix.sync.aligned.m8n8.x4.shared.b16 {%0,%1,%2,%3}, [%4];"    \
        : "=r"(r0), "=r"(r1), "=r"(r2), "=r"(r3) : "r"(addr))

#define MMA_TF32S(c, a0, a1, a2, a3, b0, b1)                               \
    asm volatile(                                                          \
        "mma.sync.aligned.m16n8k8.row.col.f32.tf32.tf32.f32 "              \
        "{%0,%1,%2,%3}, {%4,%5,%6,%7}, {%8,%9}, {%0,%1,%2,%3};"            \
        : "+f"((c)[0]), "+f"((c)[1]), "+f"((c)[2]), "+f"((c)[3])           \
        : "r"(a0), "r"(a1), "r"(a2), "r"(a3), "r"(b0), "r"(b1))

// ---- prep: W -> tf32, canonical matrix order (contiguous uint4 stores) ----
__global__ void prep_kernel(const float* __restrict__ Wm) {
    int idx = blockIdx.x * blockDim.x + threadIdx.x;   // (n, k4)
    int n  = idx >> 7;
    int k4 = idx & 127;
    float4 v = *reinterpret_cast<const float4*>(Wm + (size_t)n * F_DIM + k4 * 4);
    uint4 o;
    o.x = to_tf32(v.x); o.y = to_tf32(v.y);
    o.z = to_tf32(v.z); o.w = to_tf32(v.w);

    int k0  = k4 * 4;
    int t   = k0 >> 5;
    int kin = k0 & 31;
    int ks  = kin >> 3;
    int w   = (kin >> 2) & 1;
    int wn = n >> 6, nt = (n >> 3) & 7, g = n & 7;
    uint32_t base = (uint32_t)t * 8192 + wn * 2048 + ks * 512 +
                    nt * 64 + w * 32 + g * 4;
    *reinterpret_cast<uint4*>(g_Wfrag + base) = o;
}

__global__ __launch_bounds__(256, 2)
void adaboost_mma_kernel(const float* __restrict__ x,
                         const float* __restrict__ Wm,
                         const float* __restrict__ bvec,
                         const float* __restrict__ alphas,
                         float* __restrict__ out) {
    extern __shared__ uint32_t sm[];
    uint32_t* As = sm;                       // [2][16 regions][AREG]
    uint32_t* Bs = sm + 2 * A_WORDS;         // [2][8192] matrix order

    __shared__ float s_b[E_DIM];
    __shared__ float s_ta[E_DIM];
    __shared__ float psum[BM][4];
    __shared__ float s_rsum[BM];
    __shared__ int s_nresc;
    __shared__ uint32_t s_q[QCAP];

    const int tid  = threadIdx.x;
    const int wid  = tid >> 5;
    const int lane = tid & 31;
    const int g    = lane >> 2;
    const int tg   = lane & 3;
    const int wm   = wid & 1;      // 2 warp-rows (32 rows each)
    const int wn   = wid >> 1;     // 4 warp-cols (64 cols each)
    const int m0   = blockIdx.x * BM;

    s_b[tid]  = bvec[tid];
    s_ta[tid] = truncf(alphas[tid]);
    if (tid < BM) s_rsum[tid] = 0.0f;
    if (tid == 0) s_nresc = 0;

    const uint32_t As_u = smem_u32(As);
    const uint32_t Bs_u = smem_u32(Bs);
    // ldmatrix per-lane row-address pattern (bytes): matrix (lane>>3), row (lane&7)
    const uint32_t lmoff = ((uint32_t)(lane >> 3) * 128) + ((uint32_t)(lane & 7) * 16);

    float acc[2][8][4];
#pragma unroll
    for (int i = 0; i < 2; i++)
#pragma unroll
        for (int j = 0; j < 8; j++)
#pragma unroll
            for (int r = 0; r < 4; r++) acc[i][j][r] = 0.0f;

    // A commit mapping: thread -> row a_row (tid>>2), k-octet a_ks (tid&3).
    // Region (rt, ks) = 4 matrices [lo_klo][hi_klo][lo_khi][hi_khi].
    const int a_row = tid >> 2;
    const int a_ks  = tid & 3;
    const uint32_t a_region = (uint32_t)((a_row >> 4) * 4 + a_ks);
    const uint32_t a_dst = a_region * AREG + ((a_row >> 3) & 1) * 32 + (a_row & 7) * 4;

    // ---- prologue: chunk 0 ----
#pragma unroll
    for (int l = 0; l < 8; l++) {
        int u = tid + 256 * l;
        CP_ASYNC16(Bs_u + u * 16, (const char*)(g_Wfrag + u * 4));
    }
    CP_COMMIT();
    {
        float4 v0 = *reinterpret_cast<const float4*>(
            x + (size_t)(m0 + a_row) * F_DIM + a_ks * 8);
        float4 v1 = *reinterpret_cast<const float4*>(
            x + (size_t)(m0 + a_row) * F_DIM + a_ks * 8 + 4);
        uint4 o0, o1;
        o0.x = to_tf32(v0.x); o0.y = to_tf32(v0.y);
        o0.z = to_tf32(v0.z); o0.w = to_tf32(v0.w);
        o1.x = to_tf32(v1.x); o1.y = to_tf32(v1.y);
        o1.z = to_tf32(v1.z); o1.w = to_tf32(v1.w);
        *reinterpret_cast<uint4*>(As + a_dst) = o0;        // klo matrix
        *reinterpret_cast<uint4*>(As + a_dst + 64) = o1;   // khi matrix
    }

    // ---- main loop ----
    for (int t = 0; t < NCHUNK; t++) {
        const int p = t & 1;
        CP_WAIT_ALL();
        __syncthreads();   // A[p], B[p] visible; [p^1] free

        // issue B(t+1)
        if (t + 1 < NCHUNK) {
#pragma unroll
            for (int l = 0; l < 8; l++) {
                int u = tid + 256 * l;
                CP_ASYNC16(Bs_u + ((p ^ 1) * B_WORDS) * 4 + u * 16,
                           (const char*)(g_Wfrag + (t + 1) * B_WORDS + u * 4));
            }
        }
        CP_COMMIT();

        // A(t+1) -> regs
        float4 pa0, pa1;
        if (t + 1 < NCHUNK) {
            const int kn = (t + 1) * BK;
            pa0 = *reinterpret_cast<const float4*>(
                x + (size_t)(m0 + a_row) * F_DIM + kn + a_ks * 8);
            pa1 = *reinterpret_cast<const float4*>(
                x + (size_t)(m0 + a_row) * F_DIM + kn + a_ks * 8 + 4);
        }

        // ---- compute on buffer p (ldmatrix fragment loads) ----
        const uint32_t Au = As_u + (uint32_t)p * A_WORDS * 4 + lmoff;
        const uint32_t Bu = Bs_u + ((uint32_t)p * B_WORDS + wn * 2048) * 4 + lmoff;
#pragma unroll
        for (int ks = 0; ks < 4; ks++) {
            uint32_t afr[2][4];
#pragma unroll
            for (int mt = 0; mt < 2; mt++)
                LDSM_X4(afr[mt][0], afr[mt][1], afr[mt][2], afr[mt][3],
                        Au + (uint32_t)(((wm * 2 + mt) * 4 + ks) * AREG) * 4);
            uint32_t bfr[8][2];
#pragma unroll
            for (int ntp = 0; ntp < 4; ntp++)
                LDSM_X4(bfr[2 * ntp][0], bfr[2 * ntp][1],
                        bfr[2 * ntp + 1][0], bfr[2 * ntp + 1][1],
                        Bu + (uint32_t)(ks * 512 + ntp * 128) * 4);
#pragma unroll
            for (int mt = 0; mt < 2; mt++)
#pragma unroll
                for (int nt = 0; nt < 8; nt++)
                    MMA_TF32S(acc[mt][nt],
                              afr[mt][0], afr[mt][1], afr[mt][2], afr[mt][3],
                              bfr[nt][0], bfr[nt][1]);
        }

        // ---- commit A(t+1): cvt + 2x STS.128, conflict-free ----
        if (t + 1 < NCHUNK) {
            uint32_t* An = As + (p ^ 1) * A_WORDS;
            uint4 o0, o1;
            o0.x = to_tf32(pa0.x); o0.y = to_tf32(pa0.y);
            o0.z = to_tf32(pa0.z); o0.w = to_tf32(pa0.w);
            o1.x = to_tf32(pa1.x); o1.y = to_tf32(pa1.y);
            o1.z = to_tf32(pa1.z); o1.w = to_tf32(pa1.w);
            *reinterpret_cast<uint4*>(An + a_dst) = o0;
            *reinterpret_cast<uint4*>(An + a_dst + 64) = o1;
        }
    }

    // ---------------- epilogue ----------------
#pragma unroll
    for (int mt = 0; mt < 2; mt++) {
#pragma unroll
        for (int half = 0; half < 2; half++) {
            int rowl = wm * 32 + mt * 16 + g + half * 8;
            float s = 0.0f;
#pragma unroll
            for (int nt = 0; nt < 8; nt++) {
#pragma unroll
                for (int j = 0; j < 2; j++) {
                    int col = wn * 64 + nt * 8 + 2 * tg + j;
                    float logit = acc[mt][nt][half * 2 + j] + s_b[col];
                    if (fabsf(logit) < TAU) {
                        int qi = atomicAdd(&s_nresc, 1);
                        if (qi < QCAP) {
                            s_q[qi] = ((uint32_t)rowl << 8) | (uint32_t)col;
                        } else {
                            const float* xr = x + (size_t)(m0 + rowl) * F_DIM;
                            const float* wr = Wm + (size_t)col * F_DIM;
                            float a = 0.0f;
                            for (int f = 0; f < F_DIM; f++)
                                a = fmaf(__ldg(xr + f), __ldg(wr + f), a);
                            if (a + s_b[col] > 0.0f) s += s_ta[col];
                        }
                    } else if (logit > 0.0f) {
                        s += s_ta[col];
                    }
                }
            }
            s += __shfl_xor_sync(0xffffffffu, s, 1);
            s += __shfl_xor_sync(0xffffffffu, s, 2);
            if (tg == 0) psum[rowl][wn] = s;
        }
    }
    __syncthreads();

    // ---- warp-cooperative rescue ----
    {
        const int nresc = min(s_nresc, QCAP);
        for (int i = wid; i < nresc; i += 8) {
            uint32_t ent = s_q[i];
            int rowl = (int)(ent >> 8);
            int col  = (int)(ent & 0xFF);
            const float* xr = x + (size_t)(m0 + rowl) * F_DIM;
            const float* wr = Wm + (size_t)col * F_DIM;
            float a0 = 0.0f, a1 = 0.0f;
#pragma unroll
            for (int j = 0; j < 16; j += 2) {
                a0 = fmaf(__ldg(xr + j * 32 + lane), __ldg(wr + j * 32 + lane), a0);
                a1 = fmaf(__ldg(xr + (j + 1) * 32 + lane), __ldg(wr + (j + 1) * 32 + lane), a1);
            }
            float a = a0 + a1;
#pragma unroll
            for (int o = 16; o > 0; o >>= 1)
                a += __shfl_xor_sync(0xffffffffu, a, o);
            if (lane == 0 && a + s_b[col] > 0.0f)
                atomicAdd(&s_rsum[rowl], s_ta[col]);
        }
    }
    __syncthreads();

    if (tid < BM) {
        float s = psum[tid][0] + psum[tid][1] + psum[tid][2] + psum[tid][3]
                + s_rsum[tid];
        out[m0 + tid] = (s > 0.0f) ? 1.0f : ((s < 0.0f) ? -1.0f : 0.0f);
    }
}

extern "C" void kernel_launch(void* const* d_in, const int* in_sizes, int n_in,
                              void* d_out, int out_size) {
    const float* x      = (const float*)d_in[0];   // [N, F]
    const float* Wm     = (const float*)d_in[1];   // [E, F]
    const float* bvec   = (const float*)d_in[2];   // [E]
    const float* alphas = (const float*)d_in[3];   // [E]
    float* out = (float*)d_out;                    // [N]

    const int E = in_sizes[2];         // 256
    const int F = in_sizes[1] / E;     // 512
    const int N = in_sizes[0] / F;     // 131072

    (void)E; (void)F;
    prep_kernel<<<(E_DIM * (F_DIM / 4)) / 256, 256>>>(Wm);

    cudaFuncSetAttribute(adaboost_mma_kernel,
                         cudaFuncAttributeMaxDynamicSharedMemorySize, DSMEM_BYTES);
    adaboost_mma_kernel<<<N / BM, 256, DSMEM_BYTES>>>(x, Wm, bvec, alphas, out);
}

// round 16
// speedup vs baseline: 1.8658x; 1.0080x over previous
#include <cuda_runtime.h>
#include <cuda_bf16.h>
#include <cstdint>

// AdaBoost fused classifier via legacy mma.sync TF32 (base-ISA sm_103).
//   logits[N,E] = x[N,F] @ W[E,F]^T + b
//   pred = (logit > 0); acc = sum_e pred*trunc(alpha); out = sign(acc)
// |logit| < TAU rescued by warp-cooperative exact fp32 recompute.
//
// R15 champion (BM=64, 256 thr, 2 CTAs/SM, warp tile 32x64, ldmatrix
// fragment loads, conflict-free STS.128 A commit) with issue-order fixes:
//  - ks=0 fragment loads + MMAs fire FIRST after the barrier; the B(t+1)
//    cp.async issues are interleaved after ks=0/ks=1 and the A(t+1) LDGs
//    after them, so LSU issue overlaps MMA chains instead of fencing them.
//  - cp.async.cg (L2-only) for streamed W: no L1 pollution (zero reuse).

#define F_DIM 512
#define E_DIM 256
#define BM 64
#define BK 32
#define NCHUNK (F_DIM / BK)   // 16
#define TAU 4e-3f
#define QCAP 512

#define AREG 136                     // words per A region (4 matrices + 8 pad)
#define A_WORDS (16 * AREG)          // 2176 per buffer
#define B_WORDS 8192                 // per buffer
#define DSMEM_BYTES ((2 * A_WORDS + 2 * B_WORDS) * 4)   // 82944

// W tf32 matrix order:
//   word = t*8192 + wn*2048 + ks*512 + nt*64 + w*32 + g*4 + tg
__device__ uint32_t g_Wfrag[E_DIM * F_DIM];

static __device__ __forceinline__ uint32_t to_tf32(float x) {
    uint32_t r;
    asm("cvt.rna.tf32.f32 %0, %1;" : "=r"(r) : "f"(x));
    return r;
}
static __device__ __forceinline__ uint32_t smem_u32(const void* p) {
    uint32_t a;
    asm("{ .reg .u64 t; cvta.to.shared.u64 t, %1; cvt.u32.u64 %0, t; }"
        : "=r"(a) : "l"(p));
    return a;
}

#define CP_ASYNC16(dst, src) \
    asm volatile("cp.async.cg.shared.global [%0], [%1], 16;" \
                 :: "r"(dst), "l"(src) : "memory")
#define CP_COMMIT() asm volatile("cp.async.commit_group;" ::: "memory")
#define CP_WAIT_ALL() asm volatile("cp.async.wait_group 0;" ::: "memory")

#define LDSM_X4(r0, r1, r2, r3, addr)                                      \
    asm volatile(                                                          \
        "ldmatrix.sync.aligned.m8n8.x4.shared.b16 {%0,%1,%2,%3}, [%4];"    \
        : "=r"(r0), "=r"(r1), "=r"(r2), "=r"(r3) : "r"(addr))

#define MMA_TF32S(c, a0, a1, a2, a3, b0, b1)                               \
    asm volatile(                                                          \
        "mma.sync.aligned.m16n8k8.row.col.f32.tf32.tf32.f32 "              \
        "{%0,%1,%2,%3}, {%4,%5,%6,%7}, {%8,%9}, {%0,%1,%2,%3};"            \
        : "+f"((c)[0]), "+f"((c)[1]), "+f"((c)[2]), "+f"((c)[3])           \
        : "r"(a0), "r"(a1), "r"(a2), "r"(a3), "r"(b0), "r"(b1))

// one k-step of the warp tile: 2 A ldsm.x4, 4 B ldsm.x4, 16 MMAs
#define COMPUTE_KS(ks_) do {                                               \
    uint32_t afr[2][4];                                                    \
    _Pragma("unroll")                                                      \
    for (int mt = 0; mt < 2; mt++)                                         \
        LDSM_X4(afr[mt][0], afr[mt][1], afr[mt][2], afr[mt][3],            \
                Au + (uint32_t)(((wm * 2 + mt) * 4 + (ks_)) * AREG) * 4);  \
    uint32_t bfr[8][2];                                                    \
    _Pragma("unroll")                                                      \
    for (int ntp = 0; ntp < 4; ntp++)                                      \
        LDSM_X4(bfr[2 * ntp][0], bfr[2 * ntp][1],                          \
                bfr[2 * ntp + 1][0], bfr[2 * ntp + 1][1],                  \
                Bu + (uint32_t)((ks_) * 512 + ntp * 128) * 4);             \
    _Pragma("unroll")                                                      \
    for (int mt = 0; mt < 2; mt++)                                         \
        _Pragma("unroll")                                                  \
        for (int nt = 0; nt < 8; nt++)                                     \
            MMA_TF32S(acc[mt][nt],                                         \
                      afr[mt][0], afr[mt][1], afr[mt][2], afr[mt][3],      \
                      bfr[nt][0], bfr[nt][1]);                             \
} while (0)

// ---- prep: W -> tf32, canonical matrix order ----
__global__ void prep_kernel(const float* __restrict__ Wm) {
    int idx = blockIdx.x * blockDim.x + threadIdx.x;   // (n, k4)
    int n  = idx >> 7;
    int k4 = idx & 127;
    float4 v = *reinterpret_cast<const float4*>(Wm + (size_t)n * F_DIM + k4 * 4);
    uint4 o;
    o.x = to_tf32(v.x); o.y = to_tf32(v.y);
    o.z = to_tf32(v.z); o.w = to_tf32(v.w);

    int k0  = k4 * 4;
    int t   = k0 >> 5;
    int kin = k0 & 31;
    int ks  = kin >> 3;
    int w   = (kin >> 2) & 1;
    int wn = n >> 6, nt = (n >> 3) & 7, g = n & 7;
    uint32_t base = (uint32_t)t * 8192 + wn * 2048 + ks * 512 +
                    nt * 64 + w * 32 + g * 4;
    *reinterpret_cast<uint4*>(g_Wfrag + base) = o;
}

__global__ __launch_bounds__(256, 2)
void adaboost_mma_kernel(const float* __restrict__ x,
                         const float* __restrict__ Wm,
                         const float* __restrict__ bvec,
                         const float* __restrict__ alphas,
                         float* __restrict__ out) {
    extern __shared__ uint32_t sm[];
    uint32_t* As = sm;                       // [2][16 regions][AREG]
    uint32_t* Bs = sm + 2 * A_WORDS;         // [2][8192] matrix order

    __shared__ float s_b[E_DIM];
    __shared__ float s_ta[E_DIM];
    __shared__ float psum[BM][4];
    __shared__ float s_rsum[BM];
    __shared__ int s_nresc;
    __shared__ uint32_t s_q[QCAP];

    const int tid  = threadIdx.x;
    const int wid  = tid >> 5;
    const int lane = tid & 31;
    const int g    = lane >> 2;
    const int tg   = lane & 3;
    const int wm   = wid & 1;      // 2 warp-rows (32 rows each)
    const int wn   = wid >> 1;     // 4 warp-cols (64 cols each)
    const int m0   = blockIdx.x * BM;

    s_b[tid]  = bvec[tid];
    s_ta[tid] = truncf(alphas[tid]);
    if (tid < BM) s_rsum[tid] = 0.0f;
    if (tid == 0) s_nresc = 0;

    const uint32_t As_u = smem_u32(As);
    const uint32_t Bs_u = smem_u32(Bs);
    const uint32_t lmoff = ((uint32_t)(lane >> 3) * 128) + ((uint32_t)(lane & 7) * 16);

    float acc[2][8][4];
#pragma unroll
    for (int i = 0; i < 2; i++)
#pragma unroll
        for (int j = 0; j < 8; j++)
#pragma unroll
            for (int r = 0; r < 4; r++) acc[i][j][r] = 0.0f;

    // A commit mapping: thread -> row a_row (tid>>2), k-octet a_ks (tid&3).
    const int a_row = tid >> 2;
    const int a_ks  = tid & 3;
    const uint32_t a_region = (uint32_t)((a_row >> 4) * 4 + a_ks);
    const uint32_t a_dst = a_region * AREG + ((a_row >> 3) & 1) * 32 + (a_row & 7) * 4;

    // ---- prologue: chunk 0 ----
#pragma unroll
    for (int l = 0; l < 8; l++) {
        int u = tid + 256 * l;
        CP_ASYNC16(Bs_u + u * 16, (const char*)(g_Wfrag + u * 4));
    }
    CP_COMMIT();
    {
        float4 v0 = *reinterpret_cast<const float4*>(
            x + (size_t)(m0 + a_row) * F_DIM + a_ks * 8);
        float4 v1 = *reinterpret_cast<const float4*>(
            x + (size_t)(m0 + a_row) * F_DIM + a_ks * 8 + 4);
        uint4 o0, o1;
        o0.x = to_tf32(v0.x); o0.y = to_tf32(v0.y);
        o0.z = to_tf32(v0.z); o0.w = to_tf32(v0.w);
        o1.x = to_tf32(v1.x); o1.y = to_tf32(v1.y);
        o1.z = to_tf32(v1.z); o1.w = to_tf32(v1.w);
        *reinterpret_cast<uint4*>(As + a_dst) = o0;        // klo matrix
        *reinterpret_cast<uint4*>(As + a_dst + 64) = o1;   // khi matrix
    }

    // ---- main loop ----
    for (int t = 0; t < NCHUNK; t++) {
        const int p = t & 1;
        CP_WAIT_ALL();
        __syncthreads();   // A[p], B[p] visible; [p^1] free

        const uint32_t Au = As_u + (uint32_t)p * A_WORDS * 4 + lmoff;
        const uint32_t Bu = Bs_u + ((uint32_t)p * B_WORDS + wn * 2048) * 4 + lmoff;
        const bool more = (t + 1 < NCHUNK);

        // tensor pipe starts immediately
        COMPUTE_KS(0);

        // interleave B(t+1) issue (first half)
        if (more) {
#pragma unroll
            for (int l = 0; l < 4; l++) {
                int u = tid + 256 * l;
                CP_ASYNC16(Bs_u + ((p ^ 1) * B_WORDS) * 4 + u * 16,
                           (const char*)(g_Wfrag + (t + 1) * B_WORDS + u * 4));
            }
        }

        COMPUTE_KS(1);

        // B(t+1) second half + commit
        if (more) {
#pragma unroll
            for (int l = 4; l < 8; l++) {
                int u = tid + 256 * l;
                CP_ASYNC16(Bs_u + ((p ^ 1) * B_WORDS) * 4 + u * 16,
                           (const char*)(g_Wfrag + (t + 1) * B_WORDS + u * 4));
            }
        }
        CP_COMMIT();

        // A(t+1) -> regs
        float4 pa0, pa1;
        if (more) {
            const int kn = (t + 1) * BK;
            pa0 = *reinterpret_cast<const float4*>(
                x + (size_t)(m0 + a_row) * F_DIM + kn + a_ks * 8);
            pa1 = *reinterpret_cast<const float4*>(
                x + (size_t)(m0 + a_row) * F_DIM + kn + a_ks * 8 + 4);
        }

        COMPUTE_KS(2);
        COMPUTE_KS(3);

        // ---- commit A(t+1): cvt + 2x STS.128, conflict-free ----
        if (more) {
            uint32_t* An = As + (p ^ 1) * A_WORDS;
            uint4 o0, o1;
            o0.x = to_tf32(pa0.x); o0.y = to_tf32(pa0.y);
            o0.z = to_tf32(pa0.z); o0.w = to_tf32(pa0.w);
            o1.x = to_tf32(pa1.x); o1.y = to_tf32(pa1.y);
            o1.z = to_tf32(pa1.z); o1.w = to_tf32(pa1.w);
            *reinterpret_cast<uint4*>(An + a_dst) = o0;
            *reinterpret_cast<uint4*>(An + a_dst + 64) = o1;
        }
    }

    // ---------------- epilogue ----------------
#pragma unroll
    for (int mt = 0; mt < 2; mt++) {
#pragma unroll
        for (int half = 0; half < 2; half++) {
            int rowl = wm * 32 + mt * 16 + g + half * 8;
            float s = 0.0f;
#pragma unroll
            for (int nt = 0; nt < 8; nt++) {
#pragma unroll
                for (int j = 0; j < 2; j++) {
                    int col = wn * 64 + nt * 8 + 2 * tg + j;
                    float logit = acc[mt][nt][half * 2 + j] + s_b[col];
                    if (fabsf(logit) < TAU) {
                        int qi = atomicAdd(&s_nresc, 1);
                        if (qi < QCAP) {
                            s_q[qi] = ((uint32_t)rowl << 8) | (uint32_t)col;
                        } else {
                            const float* xr = x + (size_t)(m0 + rowl) * F_DIM;
                            const float* wr = Wm + (size_t)col * F_DIM;
                            float a = 0.0f;
                            for (int f = 0; f < F_DIM; f++)
                                a = fmaf(__ldg(xr + f), __ldg(wr + f), a);
                            if (a + s_b[col] > 0.0f) s += s_ta[col];
                        }
                    } else if (logit > 0.0f) {
                        s += s_ta[col];
                    }
                }
            }
            s += __shfl_xor_sync(0xffffffffu, s, 1);
            s += __shfl_xor_sync(0xffffffffu, s, 2);
            if (tg == 0) psum[rowl][wn] = s;
        }
    }
    __syncthreads();

    // ---- warp-cooperative rescue ----
    {
        const int nresc = min(s_nresc, QCAP);
        for (int i = wid; i < nresc; i += 8) {
            uint32_t ent = s_q[i];
            int rowl = (int)(ent >> 8);
            int col  = (int)(ent & 0xFF);
            const float* xr = x + (size_t)(m0 + rowl) * F_DIM;
            const float* wr = Wm + (size_t)col * F_DIM;
            float a0 = 0.0f, a1 = 0.0f;
#pragma unroll
            for (int j = 0; j < 16; j += 2) {
                a0 = fmaf(__ldg(xr + j * 32 + lane), __ldg(wr + j * 32 + lane), a0);
                a1 = fmaf(__ldg(xr + (j + 1) * 32 + lane), __ldg(wr + (j + 1) * 32 + lane), a1);
            }
            float a = a0 + a1;
#pragma unroll
            for (int o = 16; o > 0; o >>= 1)
                a += __shfl_xor_sync(0xffffffffu, a, o);
            if (lane == 0 && a + s_b[col] > 0.0f)
                atomicAdd(&s_rsum[rowl], s_ta[col]);
        }
    }
    __syncthreads();

    if (tid < BM) {
        float s = psum[tid][0] + psum[tid][1] + psum[tid][2] + psum[tid][3]
                + s_rsum[tid];
        out[m0 + tid] = (s > 0.0f) ? 1.0f : ((s < 0.0f) ? -1.0f : 0.0f);
    }
}

extern "C" void kernel_launch(void* const* d_in, const int* in_sizes, int n_in,
                              void* d_out, int out_size) {
    const float* x      = (const float*)d_in[0];   // [N, F]
    const float* Wm     = (const float*)d_in[1];   // [E, F]
    const float* bvec   = (const float*)d_in[2];   // [E]
    const float* alphas = (const float*)d_in[3];   // [E]
    float* out = (float*)d_out;                    // [N]

    const int E = in_sizes[2];         // 256
    const int F = in_sizes[1] / E;     // 512
    const int N = in_sizes[0] / F;     // 131072

    (void)E; (void)F;
    prep_kernel<<<(E_DIM * (F_DIM / 4)) / 256, 256>>>(Wm);

    cudaFuncSetAttribute(adaboost_mma_kernel,
                         cudaFuncAttributeMaxDynamicSharedMemorySize, DSMEM_BYTES);
    adaboost_mma_kernel<<<N / BM, 256, DSMEM_BYTES>>>(x, Wm, bvec, alphas, out);
}